// round 17
// baseline (speedup 1.0000x reference)
#include <cuda_runtime.h>
#include <cuda_fp16.h>
#include <cstdint>

// x[512,1024,64] f32, W{f,o,i,g}[128,192] f32, b*[128], Wfc[10,128], bfc[10], out[512,10] f32.
#define B_TOT    512
#define T_LEN    1024
#define I_DIM    64
#define H_DIM    128
#define C_DIM    10
#define KDIM     192
#define BPC      4
#define NTHREADS 256
#define NCTAS    (B_TOT / BPC)   // 128

#define AROW     200             // halves per acts row (400B stride -> conflict-free LDS.32)

// m16n8k16 fp16 MMA, fp32 accum, accumulate in place. Base ISA (sm_80+).
__device__ __forceinline__ void mma16816(float* d, const uint32_t* a, uint32_t b0, uint32_t b1) {
    asm volatile(
        "mma.sync.aligned.m16n8k16.row.col.f32.f16.f16.f32 "
        "{%0,%1,%2,%3}, {%4,%5,%6,%7}, {%8,%9}, {%0,%1,%2,%3};"
        : "+f"(d[0]), "+f"(d[1]), "+f"(d[2]), "+f"(d[3])
        : "r"(a[0]), "r"(a[1]), "r"(a[2]), "r"(a[3]), "r"(b0), "r"(b1));
}

__device__ __forceinline__ float sig_mufu(float z) {
    float r;
    asm("tanh.approx.f32 %0, %1;" : "=f"(r) : "f"(0.5f * z));
    return fmaf(0.5f, r, 0.5f);
}
__device__ __forceinline__ float tanh_mufu(float z) {
    float r;
    asm("tanh.approx.f32 %0, %1;" : "=f"(r) : "f"(z));
    return r;
}

__device__ __forceinline__ uint32_t pack_h2(float lo, float hi) {
    __half2 h = __floats2half2_rn(lo, hi);
    return *reinterpret_cast<uint32_t*>(&h);
}

__global__ void __launch_bounds__(NTHREADS, 1)
lstm_hmma_kernel(const float* __restrict__ x,
                 const float* __restrict__ Wf, const float* __restrict__ bf,
                 const float* __restrict__ Wo, const float* __restrict__ bo,
                 const float* __restrict__ Wi, const float* __restrict__ bi,
                 const float* __restrict__ Wg, const float* __restrict__ bg,
                 const float* __restrict__ Wfc, const float* __restrict__ bfc,
                 float* __restrict__ out)
{
    __shared__ __half actsA[8 * AROW];
    __shared__ __half actsB[8 * AROW];
    __shared__ float  hb[BPC * H_DIM];

    const int tid  = threadIdx.x;
    const int w    = tid >> 5;          // warp 0..7: owns gate-rows [16w, 16w+16)
    const int lane = tid & 31;
    const int lg   = lane >> 2;         // B column (batch) group / A row offset
    const int tt   = lane & 3;
    const int b0g  = blockIdx.x * BPC;

    const int r0 = w * 16 + lg;         // gate-local row 0
    const int r1 = r0 + 8;              // gate-local row 1

    // ---- One-time: all A fragments in registers (4 gates x 12 ks x 4 regs) ----
    // order in afr: 0=f, 1=i, 2=g, 3=o  (o last: consumed in phase 3)
    uint32_t afr[4][12][4];
    {
        const float* srcs[4] = {Wf, Wi, Wg, Wo};
#pragma unroll
        for (int gi = 0; gi < 4; ++gi) {
            const float* s = srcs[gi];
#pragma unroll
            for (int ks = 0; ks < 12; ++ks) {
                int k0 = 16 * ks + 2 * tt;
                float2 v0 = __ldg(reinterpret_cast<const float2*>(s + r0 * KDIM + k0));
                float2 v1 = __ldg(reinterpret_cast<const float2*>(s + r1 * KDIM + k0));
                float2 v2 = __ldg(reinterpret_cast<const float2*>(s + r0 * KDIM + k0 + 8));
                float2 v3 = __ldg(reinterpret_cast<const float2*>(s + r1 * KDIM + k0 + 8));
                afr[gi][ks][0] = pack_h2(v0.x, v0.y);
                afr[gi][ks][1] = pack_h2(v1.x, v1.y);
                afr[gi][ks][2] = pack_h2(v2.x, v2.y);
                afr[gi][ks][3] = pack_h2(v3.x, v3.y);
            }
        }
    }

    const float bf0 = __ldg(bf + r0), bf1 = __ldg(bf + r1);
    const float bo0 = __ldg(bo + r0), bo1 = __ldg(bo + r1);
    const float bi0 = __ldg(bi + r0), bi1 = __ldg(bi + r1);
    const float bg0 = __ldg(bg + r0), bg1 = __ldg(bg + r1);

    for (int i = tid; i < 8 * AROW / 2; i += NTHREADS) {
        reinterpret_cast<uint32_t*>(actsA)[i] = 0;
        reinterpret_cast<uint32_t*>(actsB)[i] = 0;
    }

    const int bb = tid >> 6;            // batch 0..3
    const int ff = tid & 63;            // feature 0..63
    const float* xp = x + (size_t)(b0g + bb) * T_LEN * I_DIM + ff;
    __syncthreads();
    actsA[bb * AROW + ff] = __float2half_rn(__ldg(xp));   // x(t=0)
    __syncthreads();

    float c_st[4] = {0.f, 0.f, 0.f, 0.f};

    for (int t = 0; t < T_LEN; ++t) {
        const __half* aR = (t & 1) ? actsB : actsA;
        __half*       aW = (t & 1) ? actsA : actsB;

        float xval = 0.0f;
        if (t + 1 < T_LEN) xval = __ldg(xp + (size_t)(t + 1) * I_DIM);

        // ---- Phase 1: f, i, g MMAs (3 independent chains per warp) ----
        float accf[4] = {0.f, 0.f, 0.f, 0.f};
        float acci[4] = {0.f, 0.f, 0.f, 0.f};
        float accg[4] = {0.f, 0.f, 0.f, 0.f};
#pragma unroll
        for (int ks = 0; ks < 12; ++ks) {
            const uint32_t* brow = reinterpret_cast<const uint32_t*>(aR + lg * AROW + 16 * ks);
            uint32_t b0 = brow[tt];
            uint32_t b1 = brow[tt + 4];
            mma16816(accf, afr[0][ks], b0, b1);
            mma16816(acci, afr[1][ks], b0, b1);
            mma16816(accg, afr[2][ks], b0, b1);
        }

        // ---- Phase 2: f/i/g epilogue + c update (MUFUs overlap phase-3 MMA exec) ----
        float cn[4];
#pragma unroll
        for (int q = 0; q < 4; ++q) {
            const float bfv = (q < 2) ? bf0 : bf1;
            const float biv = (q < 2) ? bi0 : bi1;
            const float bgv = (q < 2) ? bg0 : bg1;
            float fs = sig_mufu(accf[q] + bfv);
            float is = sig_mufu(acci[q] + biv);
            float gt = tanh_mufu(accg[q] + bgv);
            cn[q] = c_st[q] * fs + gt * is;
            c_st[q] = cn[q];
        }

        // ---- Phase 3: o MMAs, 2 accumulation chains (even/odd ks) ----
        float acco0[4] = {0.f, 0.f, 0.f, 0.f};
        float acco1[4] = {0.f, 0.f, 0.f, 0.f};
#pragma unroll
        for (int ks = 0; ks < 12; ks += 2) {
            const uint32_t* br0 = reinterpret_cast<const uint32_t*>(aR + lg * AROW + 16 * ks);
            const uint32_t* br1 = reinterpret_cast<const uint32_t*>(aR + lg * AROW + 16 * (ks + 1));
            uint32_t e0 = br0[tt], e1 = br0[tt + 4];
            uint32_t o0 = br1[tt], o1 = br1[tt + 4];
            mma16816(acco0, afr[3][ks],     e0, e1);
            mma16816(acco1, afr[3][ks + 1], o0, o1);
        }

        // ---- Phase 4: o epilogue, h stores, x stage, single sync ----
#pragma unroll
        for (int q = 0; q < 4; ++q) {
            const float bov = (q < 2) ? bo0 : bo1;
            const int   row = (q < 2) ? r0 : r1;
            float os = sig_mufu(acco0[q] + acco1[q] + bov);
            float h  = cn[q] * os;                  // reference: no tanh on c
            if (tt < 2) {
                int batch = 2 * tt + (q & 1);
                aW[batch * AROW + I_DIM + row] = __float2half_rn(h);
                if (t == T_LEN - 1)
                    hb[batch * H_DIM + row] = h;
            }
        }

        if (t + 1 < T_LEN)
            aW[bb * AROW + ff] = __float2half_rn(xval);

        __syncthreads();
    }

    // ---- Final FC: out[b, cc] = h[b,:] . Wfc[cc,:] + bfc[cc] ----
    if (tid < BPC * C_DIM) {
        int b  = tid / C_DIM;
        int cc = tid - b * C_DIM;
        float s = __ldg(bfc + cc);
        const float* hrow = hb + b * H_DIM;
        const float* wrow = Wfc + cc * H_DIM;
#pragma unroll 8
        for (int k = 0; k < H_DIM; ++k) s += hrow[k] * wrow[k];
        out[(b0g + b) * C_DIM + cc] = s;
    }
}

extern "C" void kernel_launch(void* const* d_in, const int* in_sizes, int n_in,
                              void* d_out, int out_size)
{
    const float* x   = (const float*)d_in[0];
    const float* Wf  = (const float*)d_in[1];
    const float* bf  = (const float*)d_in[2];
    const float* Wo  = (const float*)d_in[3];
    const float* bo  = (const float*)d_in[4];
    const float* Wi  = (const float*)d_in[5];
    const float* bi  = (const float*)d_in[6];
    const float* Wg  = (const float*)d_in[7];
    const float* bg  = (const float*)d_in[8];
    const float* Wfc = (const float*)d_in[9];
    const float* bfc = (const float*)d_in[10];
    float* out = (float*)d_out;

    lstm_hmma_kernel<<<NCTAS, NTHREADS>>>(
        x, Wf, bf, Wo, bo, Wi, bi, Wg, bg, Wfc, bfc, out);
}